// round 1
// baseline (speedup 1.0000x reference)
#include <cuda_runtime.h>
#include <math.h>

#define DTF       1e-4f
#define TSTEPS    4000000
#define SEG       32
#define TPB       256
#define STEPS_PER_CTA (SEG*TPB)                               /* 8192 */
#define NCTA      ((TSTEPS + STEPS_PER_CTA - 1)/STEPS_PER_CTA) /* 489 */
#define NCTA_PAD  512
#define NTH       (NCTA_PAD*TPB)

struct SimConsts {
    float t00,t01,t10,t11;     // Trans
    float xi00,xi01,xi10,xi11; // XiCov
    float c00,c01,c10,c11;     // Cout
    float p0dt, p1, cA, sA;    // forcing scale, freq, per-step rotation
    float x00, x01;            // initial state
    float Mpow[17][4];         // Mpow[r] = (M^SEG)^(2^r)
};
__device__ SimConsts gC;
__device__ float g_v[NTH*2];          // per-thread exclusive prefix (within CTA)
__device__ float g_csum[NCTA_PAD*2];  // per-CTA affine offset
__device__ float g_centry[NCTA_PAD*2];// per-CTA entry state

__device__ __forceinline__ void mat2mul(const float* a, const float* b, float* o) {
    o[0]=fmaf(a[0],b[0],a[1]*b[2]); o[1]=fmaf(a[0],b[1],a[1]*b[3]);
    o[2]=fmaf(a[2],b[0],a[3]*b[2]); o[3]=fmaf(a[2],b[1],a[3]*b[3]);
}

// ---------------------------------------------------------------- setup ----
__global__ void k_setup(const float* __restrict__ A, const float* __restrict__ B,
                        const float* __restrict__ E, const float* __restrict__ cov,
                        const float* __restrict__ tp, const float* __restrict__ ini)
{
    float a0=A[0],a1=A[1],a2=A[2],a3=A[3];
    float b0=B[0],b1=B[1],b2=B[2],b3=B[3];
    float e0=E[0],e1=E[1],e2=E[2],e3=E[3];
    float v0=cov[0],v1=cov[1],v2=cov[2],v3=cov[3];
    float s2 = sqrtf(2.0f);
    // cov_in @ B
    float cb0=fmaf(v0,b0,v1*b2), cb1=fmaf(v0,b1,v1*b3);
    float cb2=fmaf(v2,b0,v3*b2), cb3=fmaf(v2,b1,v3*b3);
    // XiCov = (E - cov@B)/sqrt2
    float xi0=(e0-cb0)/s2, xi1=(e1-cb1)/s2, xi2=(e2-cb2)/s2, xi3=(e3-cb3)/s2;
    // nbt = -sqrt2 * B^T
    float n0=-s2*b0, n1=-s2*b2, n2=-s2*b1, n3=-s2*b3;
    // XiCovC = XiCov @ nbt
    float xc0=fmaf(xi0,n0,xi1*n2), xc1=fmaf(xi0,n1,xi1*n3);
    float xc2=fmaf(xi2,n0,xi3*n2), xc3=fmaf(xi2,n1,xi3*n3);
    float tr[4] = { 1.0f + (a0-xc0)*DTF, (a1-xc1)*DTF,
                    (a2-xc2)*DTF, 1.0f + (a3-xc3)*DTF };
    gC.t00=tr[0]; gC.t01=tr[1]; gC.t10=tr[2]; gC.t11=tr[3];
    gC.xi00=xi0; gC.xi01=xi1; gC.xi10=xi2; gC.xi11=xi3;
    gC.c00=n0*DTF; gC.c01=n1*DTF; gC.c10=n2*DTF; gC.c11=n3*DTF;
    gC.p0dt = tp[0]*DTF;
    gC.p1   = tp[1];
    double pd = (double)tp[1] * 1e-4;
    gC.cA = (float)cos(pd); gC.sA = (float)sin(pd);
    gC.x00 = ini[0]; gC.x01 = ini[1];
    // Mpow[0] = Trans^SEG; Mpow[r] = Mpow[r-1]^2
    float P[4]={1.f,0.f,0.f,1.f}, Q[4];
    for (int k=0;k<SEG;k++){ mat2mul(tr,P,Q); P[0]=Q[0];P[1]=Q[1];P[2]=Q[2];P[3]=Q[3]; }
    for (int i=0;i<4;i++) gC.Mpow[0][i]=P[i];
    for (int r=1;r<17;r++) mat2mul(gC.Mpow[r-1], gC.Mpow[r-1], gC.Mpow[r]);
    // zero the scan padding (deterministic every launch)
    for (int g=NCTA; g<NCTA_PAD; g++){ g_csum[g*2]=0.f; g_csum[g*2+1]=0.f; }
}

// One simulated step: update state (x0,x1) with forcing rotation (cc,ss).
#define UPSTATE(d0,d1) do{                                            \
    float a0_ = fmaf(xi01,(d1),cc);  a0_ = fmaf(xi00,(d0),a0_);        \
    float a1_ = xi11*(d1);           a1_ = fmaf(xi10,(d0),a1_);        \
    float nx0_ = fmaf(t01,x1,a0_);   nx0_ = fmaf(t00,x0,nx0_);         \
    float nx1_ = fmaf(t11,x1,a1_);   nx1_ = fmaf(t10,x0,nx1_);         \
    x0=nx0_; x1=nx1_;                                                  \
    float nc_ = fmaf(cc,cA,-(ss*sA)); ss = fmaf(ss,cA,cc*sA); cc=nc_;  \
} while(0)

// ---------------------------------------------------------------- pass1 ----
__global__ void __launch_bounds__(TPB) k_pass1(const float* __restrict__ in)
{
    const int tid = threadIdx.x, blk = blockIdx.x;
    const int gid = blk*TPB + tid;
    const int s0  = gid*SEG;
    const float t00=gC.t00,t01=gC.t01,t10=gC.t10,t11=gC.t11;
    const float xi00=gC.xi00,xi01=gC.xi01,xi10=gC.xi10,xi11=gC.xi11;
    const float cA=gC.cA, sA=gC.sA, p0dt=gC.p0dt, p1=gC.p1;
    float x0=0.f, x1=0.f;
    const int rem = TSTEPS - s0;

    if (rem >= SEG) {
        const float4* p = (const float4*)(in + (size_t)s0*3);
        float4 Af = p[0];
        float sv, cv; sincosf(p1*Af.x, &sv, &cv);
        float cc = p0dt*cv, ss = p0dt*sv;
        #pragma unroll
        for (int ch=0; ch<SEG/4; ++ch) {
            float4 Av = (ch==0)? Af : p[ch*3+0];
            float4 Bv = p[ch*3+1];
            float4 Cv = p[ch*3+2];
            UPSTATE(Av.y, Av.z);
            UPSTATE(Bv.x, Bv.y);
            UPSTATE(Bv.w, Cv.x);
            UPSTATE(Cv.z, Cv.w);
        }
    } else if (rem > 0) {
        const float* p = in + (size_t)s0*3;
        float sv, cv; sincosf(p1*p[0], &sv, &cv);
        float cc = p0dt*cv, ss = p0dt*sv;
        for (int k=0;k<rem;k++){ float d0=p[k*3+1], d1=p[k*3+2]; UPSTATE(d0,d1); }
    }

    // CTA-level Kogge-Stone over affine offsets: v_i <- Mpow[r] * v_{i-2^r} + v_i
    __shared__ float sa[TPB], sb[TPB];
    float v0=x0, v1=x1;
    sa[tid]=v0; sb[tid]=v1;
    __syncthreads();
    #pragma unroll
    for (int r=0;r<8;r++){
        int off = 1<<r;
        float u0=0.f, u1=0.f;
        if (tid>=off){ u0=sa[tid-off]; u1=sb[tid-off]; }
        __syncthreads();
        float P0=gC.Mpow[r][0],P1=gC.Mpow[r][1],P2=gC.Mpow[r][2],P3=gC.Mpow[r][3];
        v0 = fmaf(P0,u0,fmaf(P1,u1,v0));
        v1 = fmaf(P2,u0,fmaf(P3,u1,v1));
        sa[tid]=v0; sb[tid]=v1;
        __syncthreads();
    }
    g_v[gid*2]   = tid ? sa[tid-1] : 0.f;   // exclusive prefix within CTA
    g_v[gid*2+1] = tid ? sb[tid-1] : 0.f;
    if (tid==TPB-1){ g_csum[blk*2]=v0; g_csum[blk*2+1]=v1; }
}

// ---------------------------------------------------------------- pass2 ----
__global__ void k_pass2()
{
    const int g = threadIdx.x;  // NCTA_PAD threads
    __shared__ float sa[NCTA_PAD], sb[NCTA_PAD];
    float v0=g_csum[g*2], v1=g_csum[g*2+1];
    sa[g]=v0; sb[g]=v1;
    __syncthreads();
    #pragma unroll
    for (int r=0;r<9;r++){
        int off = 1<<r;
        float u0=0.f, u1=0.f;
        if (g>=off){ u0=sa[g-off]; u1=sb[g-off]; }
        __syncthreads();
        float P0=gC.Mpow[8+r][0],P1=gC.Mpow[8+r][1],P2=gC.Mpow[8+r][2],P3=gC.Mpow[8+r][3];
        v0 = fmaf(P0,u0,fmaf(P1,u1,v0));
        v1 = fmaf(P2,u0,fmaf(P3,u1,v1));
        sa[g]=v0; sb[g]=v1;
        __syncthreads();
    }
    float e0 = g ? sa[g-1] : 0.f;
    float e1 = g ? sb[g-1] : 0.f;
    // + (M^STEPS_PER_CTA)^g * x0, via binary power from the Mpow table
    float X0=gC.x00, X1=gC.x01;
    #pragma unroll
    for (int r=0;r<9;r++) if ((g>>r)&1){
        float P0=gC.Mpow[8+r][0],P1=gC.Mpow[8+r][1],P2=gC.Mpow[8+r][2],P3=gC.Mpow[8+r][3];
        float n0=fmaf(P0,X0,P1*X1), n1=fmaf(P2,X0,P3*X1);
        X0=n0; X1=n1;
    }
    g_centry[g*2]   = e0 + X0;
    g_centry[g*2+1] = e1 + X1;
}

// ---------------------------------------------------------------- pass3 ----
__global__ void __launch_bounds__(TPB) k_pass3(const float* __restrict__ in,
                                               float* __restrict__ out)
{
    const int tid = threadIdx.x, blk = blockIdx.x;
    const int gid = blk*TPB + tid;
    const int s0  = gid*SEG;
    const float t00=gC.t00,t01=gC.t01,t10=gC.t10,t11=gC.t11;
    const float xi00=gC.xi00,xi01=gC.xi01,xi10=gC.xi10,xi11=gC.xi11;
    const float c00=gC.c00,c01=gC.c01,c10=gC.c10,c11=gC.c11;
    const float cA=gC.cA, sA=gC.sA, p0dt=gC.p0dt, p1=gC.p1;

    // entry state: (M^SEG)^tid * cta_entry + local exclusive prefix
    float X0 = g_centry[blk*2], X1 = g_centry[blk*2+1];
    #pragma unroll
    for (int r=0;r<8;r++) if ((tid>>r)&1){
        float P0=gC.Mpow[r][0],P1=gC.Mpow[r][1],P2=gC.Mpow[r][2],P3=gC.Mpow[r][3];
        float n0=fmaf(P0,X0,P1*X1), n1=fmaf(P2,X0,P3*X1);
        X0=n0; X1=n1;
    }
    float x0 = X0 + g_v[gid*2];
    float x1 = X1 + g_v[gid*2+1];
    const int rem = TSTEPS - s0;

    if (rem >= SEG) {
        const float4* p = (const float4*)(in + (size_t)s0*3);
        float4* q = (float4*)(out + (size_t)s0*2);
        float4 Af = p[0];
        float sv, cv; sincosf(p1*Af.x, &sv, &cv);
        float cc = p0dt*cv, ss = p0dt*sv;
        #pragma unroll
        for (int ch=0; ch<SEG/4; ++ch) {
            float4 Av = (ch==0)? Af : p[ch*3+0];
            float4 Bv = p[ch*3+1];
            float4 Cv = p[ch*3+2];
            float4 O0, O1;
            O0.x=fmaf(c00,x0,c01*x1); O0.y=fmaf(c10,x0,c11*x1); UPSTATE(Av.y,Av.z);
            O0.z=fmaf(c00,x0,c01*x1); O0.w=fmaf(c10,x0,c11*x1); UPSTATE(Bv.x,Bv.y);
            O1.x=fmaf(c00,x0,c01*x1); O1.y=fmaf(c10,x0,c11*x1); UPSTATE(Bv.w,Cv.x);
            O1.z=fmaf(c00,x0,c01*x1); O1.w=fmaf(c10,x0,c11*x1); UPSTATE(Cv.z,Cv.w);
            q[ch*2+0]=O0; q[ch*2+1]=O1;
        }
    } else if (rem > 0) {
        const float* p = in + (size_t)s0*3;
        float sv, cv; sincosf(p1*p[0], &sv, &cv);
        float cc = p0dt*cv, ss = p0dt*sv;
        for (int k=0;k<rem;k++){
            float d0=p[k*3+1], d1=p[k*3+2];
            out[(size_t)(s0+k)*2]   = fmaf(c00,x0,c01*x1);
            out[(size_t)(s0+k)*2+1] = fmaf(c10,x0,c11*x1);
            UPSTATE(d0,d1);
        }
    }
}

// --------------------------------------------------------------- launch ----
extern "C" void kernel_launch(void* const* d_in, const int* in_sizes, int n_in,
                              void* d_out, int out_size)
{
    const float* in  = (const float*)d_in[0];
    const float* A   = (const float*)d_in[1];
    const float* B   = (const float*)d_in[2];
    // d_in[3] = D (unused by the reference)
    const float* E   = (const float*)d_in[4];
    const float* cov = (const float*)d_in[5];
    const float* tp  = (const float*)d_in[6];
    const float* ini = (const float*)d_in[7];
    float* out = (float*)d_out;

    k_setup<<<1,1>>>(A,B,E,cov,tp,ini);
    k_pass1<<<NCTA,TPB>>>(in);
    k_pass2<<<1,NCTA_PAD>>>();
    k_pass3<<<NCTA,TPB>>>(in, out);
}

// round 2
// speedup vs baseline: 1.6590x; 1.6590x over previous
#include <cuda_runtime.h>
#include <math.h>

#define DTF       1e-4f
#define TSTEPS    4000000
#define SEG       16
#define TPB       256
#define STEPS_PER_CTA (SEG*TPB)                                /* 4096 */
#define NCTA      ((TSTEPS + STEPS_PER_CTA - 1)/STEPS_PER_CTA) /* 977  */
#define NCTA_PAD  1024
#define NTH       (NCTA_PAD*TPB)

// smem geometry (float4 units)
#define IN_ROW    13          /* 12 payload float4 + 1 pad  (48 floats/seg) */
#define OUT_ROW   9           /* 8 payload float4 + 1 pad   (32 floats/seg) */
#define WARP_IN   (32*IN_ROW)   /* 416 f4 = 6656 B  */
#define WARP_OUT  (32*OUT_ROW)  /* 288 f4 = 4608 B  */
#define P1_SMEM   (8*WARP_IN*16)            /* 53248 B */
#define P3_SMEM   (8*(WARP_IN+WARP_OUT)*16) /* 90112 B */

struct SimConsts {
    float t00,t01,t10,t11;     // Trans
    float xi00,xi01,xi10,xi11; // XiCov
    float c00,c01,c10,c11;     // Cout
    float p0dt, p1, cA, sA;    // forcing scale, freq, per-step rotation
    float x00, x01;            // initial state
    float Mpow[18][4];         // Mpow[r] = (M^SEG)^(2^r)
};
__device__ SimConsts gC;
__device__ float g_v[NTH*2];          // per-thread exclusive prefix (within CTA)
__device__ float g_csum[NCTA_PAD*2];  // per-CTA affine offset
__device__ float g_centry[NCTA_PAD*2];// per-CTA entry state

__device__ __forceinline__ void mat2mul(const float* a, const float* b, float* o) {
    o[0]=fmaf(a[0],b[0],a[1]*b[2]); o[1]=fmaf(a[0],b[1],a[1]*b[3]);
    o[2]=fmaf(a[2],b[0],a[3]*b[2]); o[3]=fmaf(a[2],b[1],a[3]*b[3]);
}

// ---------------------------------------------------------------- setup ----
__global__ void k_setup(const float* __restrict__ A, const float* __restrict__ B,
                        const float* __restrict__ E, const float* __restrict__ cov,
                        const float* __restrict__ tp, const float* __restrict__ ini)
{
    float a0=A[0],a1=A[1],a2=A[2],a3=A[3];
    float b0=B[0],b1=B[1],b2=B[2],b3=B[3];
    float e0=E[0],e1=E[1],e2=E[2],e3=E[3];
    float v0=cov[0],v1=cov[1],v2=cov[2],v3=cov[3];
    float s2 = sqrtf(2.0f);
    float cb0=fmaf(v0,b0,v1*b2), cb1=fmaf(v0,b1,v1*b3);
    float cb2=fmaf(v2,b0,v3*b2), cb3=fmaf(v2,b1,v3*b3);
    float xi0=(e0-cb0)/s2, xi1=(e1-cb1)/s2, xi2=(e2-cb2)/s2, xi3=(e3-cb3)/s2;
    float n0=-s2*b0, n1=-s2*b2, n2=-s2*b1, n3=-s2*b3;
    float xc0=fmaf(xi0,n0,xi1*n2), xc1=fmaf(xi0,n1,xi1*n3);
    float xc2=fmaf(xi2,n0,xi3*n2), xc3=fmaf(xi2,n1,xi3*n3);
    float tr[4] = { 1.0f + (a0-xc0)*DTF, (a1-xc1)*DTF,
                    (a2-xc2)*DTF, 1.0f + (a3-xc3)*DTF };
    gC.t00=tr[0]; gC.t01=tr[1]; gC.t10=tr[2]; gC.t11=tr[3];
    gC.xi00=xi0; gC.xi01=xi1; gC.xi10=xi2; gC.xi11=xi3;
    gC.c00=n0*DTF; gC.c01=n1*DTF; gC.c10=n2*DTF; gC.c11=n3*DTF;
    gC.p0dt = tp[0]*DTF;
    gC.p1   = tp[1];
    double pd = (double)tp[1] * 1e-4;
    gC.cA = (float)cos(pd); gC.sA = (float)sin(pd);
    gC.x00 = ini[0]; gC.x01 = ini[1];
    float P[4]={1.f,0.f,0.f,1.f}, Q[4];
    for (int k=0;k<SEG;k++){ mat2mul(tr,P,Q); P[0]=Q[0];P[1]=Q[1];P[2]=Q[2];P[3]=Q[3]; }
    for (int i=0;i<4;i++) gC.Mpow[0][i]=P[i];
    for (int r=1;r<18;r++) mat2mul(gC.Mpow[r-1], gC.Mpow[r-1], gC.Mpow[r]);
    for (int g=NCTA; g<NCTA_PAD; g++){ g_csum[g*2]=0.f; g_csum[g*2+1]=0.f; }
}

// One simulated step: update state (x0,x1) with forcing rotation (cc,ss).
#define UPSTATE(d0,d1) do{                                            \
    float a0_ = fmaf(xi01,(d1),cc);  a0_ = fmaf(xi00,(d0),a0_);        \
    float a1_ = xi11*(d1);           a1_ = fmaf(xi10,(d0),a1_);        \
    float nx0_ = fmaf(t01,x1,a0_);   nx0_ = fmaf(t00,x0,nx0_);         \
    float nx1_ = fmaf(t11,x1,a1_);   nx1_ = fmaf(t10,x0,nx1_);         \
    x0=nx0_; x1=nx1_;                                                  \
    float nc_ = fmaf(cc,cA,-(ss*sA)); ss = fmaf(ss,cA,cc*sA); cc=nc_;  \
} while(0)

#define OUTPAIR(o0,o1) do{ (o0)=fmaf(c00,x0,c01*x1); (o1)=fmaf(c10,x0,c11*x1); }while(0)

// ---------------------------------------------------------------- pass1 ----
__global__ void __launch_bounds__(TPB) k_pass1(const float* __restrict__ in)
{
    extern __shared__ float4 s4[];
    const int tid = threadIdx.x, blk = blockIdx.x;
    const int lane = tid & 31, wid = tid >> 5;
    const int gid = blk*TPB + tid;
    const float t00=gC.t00,t01=gC.t01,t10=gC.t10,t11=gC.t11;
    const float xi00=gC.xi00,xi01=gC.xi01,xi10=gC.xi10,xi11=gC.xi11;
    const float cA=gC.cA, sA=gC.sA, p0dt=gC.p0dt, p1=gC.p1;
    float x0=0.f, x1=0.f;

    const int warpStepBase = (blk*TPB + wid*32)*SEG;   // 512 steps per warp tile
    float4* sin4 = s4 + wid*WARP_IN;

    if (warpStepBase + 32*SEG <= TSTEPS) {
        // ---- fast path: coalesced stage of the full warp tile ----
        const float4* p4 = (const float4*)in + (size_t)warpStepBase*3/4;
        #pragma unroll
        for (int i=0;i<12;i++){
            int q = lane + 32*i;             // 0..383 float4s
            float4 v = p4[q];
            int to = q/12, c = q - to*12;
            sin4[to*IN_ROW + c] = v;
        }
        __syncwarp();
        const float4* row = sin4 + lane*IN_ROW;
        float cc=0.f, ss=0.f;
        #pragma unroll
        for (int j=0;j<4;j++){
            float4 a=row[3*j], b=row[3*j+1], c=row[3*j+2];
            if (j==0){ float sv,cv; sincosf(p1*a.x,&sv,&cv); cc=p0dt*cv; ss=p0dt*sv; }
            UPSTATE(a.y,a.z);
            UPSTATE(b.x,b.y);
            UPSTATE(b.w,c.x);
            UPSTATE(c.z,c.w);
        }
    } else {
        // ---- tail: per-thread scalar (segments are full or empty) ----
        const int s0 = gid*SEG;
        if (s0 < TSTEPS) {
            const float* p = in + (size_t)s0*3;
            float sv,cv; sincosf(p1*p[0],&sv,&cv);
            float cc=p0dt*cv, ss=p0dt*sv;
            #pragma unroll
            for (int k=0;k<SEG;k++){ float d0=p[k*3+1], d1=p[k*3+2]; UPSTATE(d0,d1); }
        }
    }

    // CTA-level Kogge-Stone over affine offsets
    __shared__ float sa[TPB], sb[TPB];
    float v0=x0, v1=x1;
    sa[tid]=v0; sb[tid]=v1;
    __syncthreads();
    #pragma unroll
    for (int r=0;r<8;r++){
        int off = 1<<r;
        float u0=0.f, u1=0.f;
        if (tid>=off){ u0=sa[tid-off]; u1=sb[tid-off]; }
        __syncthreads();
        float P0=gC.Mpow[r][0],P1=gC.Mpow[r][1],P2=gC.Mpow[r][2],P3=gC.Mpow[r][3];
        v0 = fmaf(P0,u0,fmaf(P1,u1,v0));
        v1 = fmaf(P2,u0,fmaf(P3,u1,v1));
        sa[tid]=v0; sb[tid]=v1;
        __syncthreads();
    }
    g_v[gid*2]   = tid ? sa[tid-1] : 0.f;
    g_v[gid*2+1] = tid ? sb[tid-1] : 0.f;
    if (tid==TPB-1){ g_csum[blk*2]=v0; g_csum[blk*2+1]=v1; }
}

// ---------------------------------------------------------------- pass2 ----
__global__ void k_pass2()
{
    const int g = threadIdx.x;  // NCTA_PAD = 1024 threads
    __shared__ float sa[NCTA_PAD], sb[NCTA_PAD];
    float v0=g_csum[g*2], v1=g_csum[g*2+1];
    sa[g]=v0; sb[g]=v1;
    __syncthreads();
    #pragma unroll
    for (int r=0;r<10;r++){
        int off = 1<<r;
        float u0=0.f, u1=0.f;
        if (g>=off){ u0=sa[g-off]; u1=sb[g-off]; }
        __syncthreads();
        float P0=gC.Mpow[8+r][0],P1=gC.Mpow[8+r][1],P2=gC.Mpow[8+r][2],P3=gC.Mpow[8+r][3];
        v0 = fmaf(P0,u0,fmaf(P1,u1,v0));
        v1 = fmaf(P2,u0,fmaf(P3,u1,v1));
        sa[g]=v0; sb[g]=v1;
        __syncthreads();
    }
    float e0 = g ? sa[g-1] : 0.f;
    float e1 = g ? sb[g-1] : 0.f;
    float X0=gC.x00, X1=gC.x01;
    #pragma unroll
    for (int r=0;r<10;r++) if ((g>>r)&1){
        float P0=gC.Mpow[8+r][0],P1=gC.Mpow[8+r][1],P2=gC.Mpow[8+r][2],P3=gC.Mpow[8+r][3];
        float n0=fmaf(P0,X0,P1*X1), n1=fmaf(P2,X0,P3*X1);
        X0=n0; X1=n1;
    }
    g_centry[g*2]   = e0 + X0;
    g_centry[g*2+1] = e1 + X1;
}

// ---------------------------------------------------------------- pass3 ----
__global__ void __launch_bounds__(TPB) k_pass3(const float* __restrict__ in,
                                               float* __restrict__ out)
{
    extern __shared__ float4 s4[];
    const int tid = threadIdx.x, blk = blockIdx.x;
    const int lane = tid & 31, wid = tid >> 5;
    const int gid = blk*TPB + tid;
    const float t00=gC.t00,t01=gC.t01,t10=gC.t10,t11=gC.t11;
    const float xi00=gC.xi00,xi01=gC.xi01,xi10=gC.xi10,xi11=gC.xi11;
    const float c00=gC.c00,c01=gC.c01,c10=gC.c10,c11=gC.c11;
    const float cA=gC.cA, sA=gC.sA, p0dt=gC.p0dt, p1=gC.p1;

    // entry state: (M^SEG)^tid * cta_entry + local exclusive prefix
    float X0 = g_centry[blk*2], X1 = g_centry[blk*2+1];
    #pragma unroll
    for (int r=0;r<8;r++) if ((tid>>r)&1){
        float P0=gC.Mpow[r][0],P1=gC.Mpow[r][1],P2=gC.Mpow[r][2],P3=gC.Mpow[r][3];
        float n0=fmaf(P0,X0,P1*X1), n1=fmaf(P2,X0,P3*X1);
        X0=n0; X1=n1;
    }
    float x0 = X0 + g_v[gid*2];
    float x1 = X1 + g_v[gid*2+1];

    const int warpStepBase = (blk*TPB + wid*32)*SEG;
    float4* sin4  = s4 + wid*WARP_IN;
    float4* sout4 = s4 + 8*WARP_IN + wid*WARP_OUT;

    if (warpStepBase + 32*SEG <= TSTEPS) {
        // ---- stage input coalesced ----
        const float4* p4 = (const float4*)in + (size_t)warpStepBase*3/4;
        #pragma unroll
        for (int i=0;i<12;i++){
            int q = lane + 32*i;
            float4 v = p4[q];
            int to = q/12, c = q - to*12;
            sin4[to*IN_ROW + c] = v;
        }
        __syncwarp();
        const float4* row  = sin4 + lane*IN_ROW;
        float4*       orow = sout4 + lane*OUT_ROW;
        float cc=0.f, ss=0.f;
        #pragma unroll
        for (int j=0;j<4;j++){
            float4 a=row[3*j], b=row[3*j+1], c=row[3*j+2];
            if (j==0){ float sv,cv; sincosf(p1*a.x,&sv,&cv); cc=p0dt*cv; ss=p0dt*sv; }
            float4 O0, O1;
            OUTPAIR(O0.x,O0.y); UPSTATE(a.y,a.z);
            OUTPAIR(O0.z,O0.w); UPSTATE(b.x,b.y);
            OUTPAIR(O1.x,O1.y); UPSTATE(b.w,c.x);
            OUTPAIR(O1.z,O1.w); UPSTATE(c.z,c.w);
            orow[2*j]   = O0;
            orow[2*j+1] = O1;
        }
        __syncwarp();
        // ---- coalesced store of the 4KB out tile ----
        float4* q4 = (float4*)out + (size_t)warpStepBase/2;
        #pragma unroll
        for (int i=0;i<8;i++){
            int q = lane + 32*i;             // 0..255
            int to = q>>3, c = q&7;
            q4[q] = sout4[to*OUT_ROW + c];
        }
    } else {
        const int s0 = gid*SEG;
        if (s0 < TSTEPS) {
            const float* p = in + (size_t)s0*3;
            float sv,cv; sincosf(p1*p[0],&sv,&cv);
            float cc=p0dt*cv, ss=p0dt*sv;
            #pragma unroll
            for (int k=0;k<SEG;k++){
                float d0=p[k*3+1], d1=p[k*3+2];
                out[(size_t)(s0+k)*2]   = fmaf(c00,x0,c01*x1);
                out[(size_t)(s0+k)*2+1] = fmaf(c10,x0,c11*x1);
                UPSTATE(d0,d1);
            }
        }
    }
}

// --------------------------------------------------------------- launch ----
extern "C" void kernel_launch(void* const* d_in, const int* in_sizes, int n_in,
                              void* d_out, int out_size)
{
    const float* in  = (const float*)d_in[0];
    const float* A   = (const float*)d_in[1];
    const float* B   = (const float*)d_in[2];
    // d_in[3] = D (unused by the reference)
    const float* E   = (const float*)d_in[4];
    const float* cov = (const float*)d_in[5];
    const float* tp  = (const float*)d_in[6];
    const float* ini = (const float*)d_in[7];
    float* out = (float*)d_out;

    cudaFuncSetAttribute(k_pass1, cudaFuncAttributeMaxDynamicSharedMemorySize, P1_SMEM);
    cudaFuncSetAttribute(k_pass3, cudaFuncAttributeMaxDynamicSharedMemorySize, P3_SMEM);

    k_setup<<<1,1>>>(A,B,E,cov,tp,ini);
    k_pass1<<<NCTA,TPB,P1_SMEM>>>(in);
    k_pass2<<<1,NCTA_PAD>>>();
    k_pass3<<<NCTA,TPB,P3_SMEM>>>(in, out);
}